// round 11
// baseline (speedup 1.0000x reference)
#include <cuda_runtime.h>

// MPSClassifier: B=16384, D=784, BOND=5, OUT=10
// fwd/bwd chain split + f32x2 packed math: each thread carries TWO batch
// elements in the two fp32 lanes of 64-bit registers (SASS FFMA2).
// Cores are stored in smem pre-duplicated {C0,C0,D1,D1} so one LDS.128
// feeds both lanes; x pairs are stored column-major so one LDS.64 returns
// the packed {x_lo,x_hi} operand directly.

#define TPB    64
#define EPT    2
#define ROWS   (TPB * EPT)        // 128 batch rows per CTA
#define TILE   56                 // 784 = 14*56; 7 tiles per half-chain
#define SITEQ  26                 // float4 slots per site (25 used + pad)
#define XPITCH 130                // floats per x column (2*TPB + 2, even => 8B-aligned LDS.64)
#define DIM    784
#define BATCH  16384
#define NOUT   10
#define NBLK   (BATCH / ROWS)     // 128 CTAs per direction

typedef unsigned long long u64;

__device__ float g_fwd[5 * BATCH];
__device__ float g_bwd[5 * BATCH];

static __device__ __forceinline__ u64 fma2(u64 a, u64 b, u64 c) {
    u64 d; asm("fma.rn.f32x2 %0,%1,%2,%3;" : "=l"(d) : "l"(a), "l"(b), "l"(c)); return d;
}
static __device__ __forceinline__ u64 mul2(u64 a, u64 b) {
    u64 d; asm("mul.rn.f32x2 %0,%1,%2;" : "=l"(d) : "l"(a), "l"(b)); return d;
}
static __device__ __forceinline__ u64 pack2(float lo, float hi) {
    u64 d; asm("mov.b64 %0,{%1,%2};" : "=l"(d) : "f"(lo), "f"(hi)); return d;
}
static __device__ __forceinline__ void unpack2(u64 v, float& lo, float& hi) {
    asm("mov.b64 {%0,%1},%2;" : "=f"(lo), "=f"(hi) : "l"(v));
}

// cooperative tile fill: x block [blk*ROWS, +128) x [t0, +56) into s_x[col][row],
// and duplicated cores for sites t0..t0+55 (site d uses mid core m=d-1).
static __device__ __forceinline__ void load_tile(const float* __restrict__ x,
                                                 const float* __restrict__ cm,
                                                 float4* s_c4, float* s_x,
                                                 int blk, int t0, int tid)
{
    for (int i4 = tid; i4 < ROWS * (TILE / 4); i4 += TPB) {
        int rr = i4 / (TILE / 4), c4 = i4 % (TILE / 4);
        const float4 v = *(const float4*)(x + (size_t)(blk * ROWS + rr) * DIM + t0 + c4 * 4);
        s_x[(c4 * 4 + 0) * XPITCH + rr] = v.x;
        s_x[(c4 * 4 + 1) * XPITCH + rr] = v.y;
        s_x[(c4 * 4 + 2) * XPITCH + rr] = v.z;
        s_x[(c4 * 4 + 3) * XPITCH + rr] = v.w;
    }
    for (int e = tid; e < TILE * 25; e += TPB) {
        int j = e / 25, p = e - j * 25;
        int m = t0 + j - 1;
        if (m >= 0 && m <= 781) {
            int l = p / 5, r = p - l * 5;
            float a0 = cm[m * 50 + l * 10 + r];
            float a1 = cm[m * 50 + l * 10 + 5 + r];
            s_c4[j * SITEQ + p] = make_float4(a0, a0, a1 - a0, a1 - a0);
        }
    }
}

__global__ __launch_bounds__(TPB, 2)
void mps_chain(const float* __restrict__ x,
               const float* __restrict__ cf,
               const float* __restrict__ cm,
               const float* __restrict__ cl)
{
    extern __shared__ float smem[];
    float4* s_c4 = (float4*)smem;                    // 56*26 float4 = 23,296 B
    float*  s_x  = smem + TILE * SITEQ * 4;          // 56*130 floats = 29,120 B

    const int  tid = threadIdx.x;
    const bool bwd = blockIdx.x >= NBLK;
    const int  blk = bwd ? blockIdx.x - NBLK : blockIdx.x;
    const int  b0  = blk * ROWS + 2 * tid;

    u64 c2[5];

    if (!bwd) {
        // ============ FORWARD: sites 0..391 ============
        for (int it = 0; it < 7; it++) {
            int t0 = it * TILE;
            __syncthreads();
            load_tile(x, cm, s_c4, s_x, blk, t0, tid);
            __syncthreads();

            int j0 = 0;
            if (it == 0) {
                float x0 = s_x[2 * tid], x1 = s_x[2 * tid + 1];
#pragma unroll
                for (int r = 0; r < 5; r++) {
                    float a = cf[r], d = cf[5 + r] - a;
                    c2[r] = pack2(fmaf(x0, d, a), fmaf(x1, d, a));
                }
                j0 = 1;
            }
#pragma unroll 2
            for (int j = j0; j < TILE; j++) {
                const ulonglong2* cp = (const ulonglong2*)(s_c4 + j * SITEQ);
                ulonglong2 q[25];
#pragma unroll
                for (int p = 0; p < 25; p++) q[p] = cp[p];
                u64 xv = *(const u64*)(s_x + j * XPITCH + 2 * tid);
                u64 v0[5], v1[5];
#pragma unroll
                for (int r = 0; r < 5; r++) {
                    v0[r] = mul2(c2[0], q[r].x);
                    v1[r] = mul2(c2[0], q[r].y);
                }
#pragma unroll
                for (int l = 1; l < 5; l++)
#pragma unroll
                    for (int r = 0; r < 5; r++) {
                        v0[r] = fma2(c2[l], q[l * 5 + r].x, v0[r]);
                        v1[r] = fma2(c2[l], q[l * 5 + r].y, v1[r]);
                    }
#pragma unroll
                for (int r = 0; r < 5; r++) c2[r] = fma2(xv, v1[r], v0[r]);
            }
        }
#pragma unroll
        for (int r = 0; r < 5; r++) {
            float lo, hi; unpack2(c2[r], lo, hi);
            g_fwd[r * BATCH + b0]     = lo;
            g_fwd[r * BATCH + b0 + 1] = hi;
        }
    } else {
        // ============ BACKWARD: sites 783..392 ============
        for (int it = 0; it < 7; it++) {
            int t0 = 728 - it * TILE;
            __syncthreads();
            load_tile(x, cm, s_c4, s_x, blk, t0, tid);
            __syncthreads();

            int jhi = TILE - 1;
            if (it == 0) {
                float x0 = s_x[(TILE - 1) * XPITCH + 2 * tid];
                float x1 = s_x[(TILE - 1) * XPITCH + 2 * tid + 1];
#pragma unroll
                for (int l = 0; l < 5; l++) {
                    float a = cl[2 * l], d = cl[2 * l + 1] - a;
                    c2[l] = pack2(fmaf(x0, d, a), fmaf(x1, d, a));
                }
                jhi = TILE - 2;
            }
#pragma unroll 2
            for (int j = jhi; j >= 0; j--) {        // w <- M_d w
                const ulonglong2* cp = (const ulonglong2*)(s_c4 + j * SITEQ);
                ulonglong2 q[25];
#pragma unroll
                for (int p = 0; p < 25; p++) q[p] = cp[p];
                u64 xv = *(const u64*)(s_x + j * XPITCH + 2 * tid);
                u64 v0[5], v1[5];
#pragma unroll
                for (int l = 0; l < 5; l++) {
                    v0[l] = mul2(c2[0], q[l * 5].x);
                    v1[l] = mul2(c2[0], q[l * 5].y);
                }
#pragma unroll
                for (int r = 1; r < 5; r++)
#pragma unroll
                    for (int l = 0; l < 5; l++) {
                        v0[l] = fma2(c2[r], q[l * 5 + r].x, v0[l]);
                        v1[l] = fma2(c2[r], q[l * 5 + r].y, v1[l]);
                    }
#pragma unroll
                for (int l = 0; l < 5; l++) c2[l] = fma2(xv, v1[l], v0[l]);
            }
        }
#pragma unroll
        for (int l = 0; l < 5; l++) {
            float lo, hi; unpack2(c2[l], lo, hi);
            g_bwd[l * BATCH + b0]     = lo;
            g_bwd[l * BATCH + b0 + 1] = hi;
        }
    }
}

__global__ __launch_bounds__(256)
void mps_epilogue(const float* __restrict__ fc_w,
                  const float* __restrict__ fc_b,
                  float* __restrict__ out)
{
    const int b = blockIdx.x * 256 + threadIdx.x;
    float acc = 0.0f;
#pragma unroll
    for (int r = 0; r < 5; r++)
        acc = fmaf(g_fwd[r * BATCH + b], g_bwd[r * BATCH + b], acc);
#pragma unroll
    for (int o = 0; o < NOUT; o++)
        out[(size_t)b * NOUT + o] = fmaf(acc, fc_w[o], fc_b[o]);
}

extern "C" void kernel_launch(void* const* d_in, const int* in_sizes, int n_in,
                              void* d_out, int out_size)
{
    const float* x          = (const float*)d_in[0];
    const float* core_first = (const float*)d_in[1];
    const float* cores_mid  = (const float*)d_in[2];
    const float* core_last  = (const float*)d_in[3];
    const float* fc_w       = (const float*)d_in[4];
    const float* fc_b       = (const float*)d_in[5];
    float* out              = (float*)d_out;

    const int smem_bytes = (TILE * SITEQ * 4 + TILE * XPITCH) * (int)sizeof(float); // 52,416 B
    cudaFuncSetAttribute(mps_chain, cudaFuncAttributeMaxDynamicSharedMemorySize,
                         smem_bytes);

    mps_chain<<<2 * NBLK, TPB, smem_bytes>>>(x, core_first, cores_mid, core_last);
    mps_epilogue<<<BATCH / 256, 256>>>(fc_w, fc_b, out);
}